// round 14
// baseline (speedup 1.0000x reference)
#include <cuda_runtime.h>

#define N_NODES 100000
#define N_EDGES 6400000
#define F       32
#define FIN     10
#define FOUT    4
#define STRIDE  128   // bucket capacity; deg~Poisson(64), 8 sigma, P(ovfl)~1e-10

// Scratch (device globals; no allocation allowed)
__device__ int   d_cursor[N_NODES];
__device__ float d_dinv  [N_NODES];
__device__ float d_g1    [N_NODES * F];
__device__ float d_g2    [N_NODES * F];
__device__ int   d_csr   [N_NODES * STRIDE];

// ---------------------------------------------------------------------------
// Bucketed fill: pos = atomicAdd(cursor[dst]); csr[dst*STRIDE+pos] = src
// cursor[v] doubles as in-degree afterwards.
// ---------------------------------------------------------------------------
__global__ void k_zero() {
    int v = blockIdx.x * blockDim.x + threadIdx.x;
    if (v < N_NODES) d_cursor[v] = 0;
}

__global__ void k_fill(const int* __restrict__ src, const int* __restrict__ dst) {
    int t = blockIdx.x * blockDim.x + threadIdx.x;           // E/4 threads
    if (t * 4 >= N_EDGES) return;
    int4 s = ((const int4*)src)[t];
    int4 d = ((const int4*)dst)[t];
    d_csr[(d.x << 7) + atomicAdd(&d_cursor[d.x], 1)] = s.x;
    d_csr[(d.y << 7) + atomicAdd(&d_cursor[d.y], 1)] = s.y;
    d_csr[(d.z << 7) + atomicAdd(&d_cursor[d.z], 1)] = s.z;
    d_csr[(d.w << 7) + atomicAdd(&d_cursor[d.w], 1)] = s.w;
}

// ---------------------------------------------------------------------------
// Layer-1 node transform: dinv = rsqrt(deg+1); g1 = dinv * (x @ W1)
// ---------------------------------------------------------------------------
__global__ void k_node1(const float* __restrict__ x, const float* __restrict__ W1) {
    __shared__ float sW[FIN * F];
    for (int i = threadIdx.x; i < FIN * F; i += blockDim.x) sW[i] = W1[i];
    __syncthreads();

    int v = blockIdx.x * blockDim.x + threadIdx.x;
    if (v >= N_NODES) return;

    float di = rsqrtf((float)(d_cursor[v] + 1));             // +1: self loop
    d_dinv[v] = di;

    float xi[FIN];
#pragma unroll
    for (int k = 0; k < FIN; k++) xi[k] = x[v * FIN + k];

#pragma unroll
    for (int j0 = 0; j0 < F; j0 += 4) {
        float4 s = make_float4(0.f, 0.f, 0.f, 0.f);
#pragma unroll
        for (int k = 0; k < FIN; k++) {
            float4 w = *(const float4*)&sW[k * F + j0];
            s.x += xi[k] * w.x; s.y += xi[k] * w.y;
            s.z += xi[k] * w.z; s.w += xi[k] * w.w;
        }
        s.x *= di; s.y *= di; s.z *= di; s.w *= di;
        *(float4*)&d_g1[v * F + j0] = s;
    }
}

// ---------------------------------------------------------------------------
// Pull-gather: warp per node; 8 lanes per edge (16B fp32 chunk each).
// One warp LDG.128 covers 4 edges; explicit MLP=4 (two half-batches of 4
// independent LDG.128s into named regs); 4 independent float4 accumulators;
// zero conversion instructions. Returns: lane L holds feature L.
// ---------------------------------------------------------------------------
__device__ __forceinline__ float warp_gather_sum(const float* __restrict__ g,
                                                 int v, int lane) {
    const int beg = v << 7;             // v * STRIDE
    const int cnt = d_cursor[v];
    const int end = beg + cnt;
    const int q   = lane >> 3;          // edge slot 0..3 within an LDG
    const int fl  = lane & 7;           // feature quad 0..7
    const float4* gv = (const float4*)g;

    float4 aA = make_float4(0.f, 0.f, 0.f, 0.f);
    float4 aB = make_float4(0.f, 0.f, 0.f, 0.f);
    float4 aC = make_float4(0.f, 0.f, 0.f, 0.f);
    float4 aD = make_float4(0.f, 0.f, 0.f, 0.f);

    int e = beg;
    for (; e + 32 <= end; e += 32) {
        int my_s = __ldg(&d_csr[e + lane]) << 3;   // row base in float4 units
#pragma unroll
        for (int h = 0; h < 2; h++) {
            // 4 independent LDG.128 in flight
            int sA = __shfl_sync(0xffffffffu, my_s, (8 * h + 0) * 4 + q);
            int sB = __shfl_sync(0xffffffffu, my_s, (8 * h + 2) * 4 + q);
            int sC = __shfl_sync(0xffffffffu, my_s, (8 * h + 4) * 4 + q);
            int sD = __shfl_sync(0xffffffffu, my_s, (8 * h + 6) * 4 + q);
            // note: shuffle src = 4*j + q with j in {4h,4h+1,4h+2,4h+3}
            // rewritten: j*4+q  ->  (4h+u)*4+q
            float4 pA = __ldg(&gv[((__shfl_sync(0xffffffffu, my_s, (4 * h + 0) * 4 + q)) ) + fl]);
            float4 pB = __ldg(&gv[((__shfl_sync(0xffffffffu, my_s, (4 * h + 1) * 4 + q)) ) + fl]);
            float4 pC = __ldg(&gv[((__shfl_sync(0xffffffffu, my_s, (4 * h + 2) * 4 + q)) ) + fl]);
            float4 pD = __ldg(&gv[((__shfl_sync(0xffffffffu, my_s, (4 * h + 3) * 4 + q)) ) + fl]);
            (void)sA; (void)sB; (void)sC; (void)sD;
            aA.x += pA.x; aA.y += pA.y; aA.z += pA.z; aA.w += pA.w;
            aB.x += pB.x; aB.y += pB.y; aB.z += pB.z; aB.w += pB.w;
            aC.x += pC.x; aC.y += pC.y; aC.z += pC.z; aC.w += pC.w;
            aD.x += pD.x; aD.y += pD.y; aD.z += pD.z; aD.w += pD.w;
        }
    }
    int rem = end - e;
    if (rem > 0) {
        int my_s = ((lane < rem) ? __ldg(&d_csr[e + lane]) : 0) << 3;
        int nj = (rem + 3) >> 2;
        for (int j = 0; j < nj; j++) {
            int idx = 4 * j + q;
            int s = __shfl_sync(0xffffffffu, my_s, idx < rem ? idx : 0);
            if (idx < rem) {
                float4 p = __ldg(&gv[s + fl]);
                aA.x += p.x; aA.y += p.y; aA.z += p.z; aA.w += p.w;
            }
        }
    }
    if (q == 0) {                        // self loop once
        float4 p = __ldg(&gv[(v << 3) + fl]);
        aA.x += p.x; aA.y += p.y; aA.z += p.z; aA.w += p.w;
    }

    float4 acc;
    acc.x = (aA.x + aB.x) + (aC.x + aD.x);
    acc.y = (aA.y + aB.y) + (aC.y + aD.y);
    acc.z = (aA.z + aB.z) + (aC.z + aD.z);
    acc.w = (aA.w + aB.w) + (aC.w + aD.w);

    // fold the 4 edge slots (lanes with same fl differ in bits 3,4)
#pragma unroll
    for (int off = 8; off < 32; off <<= 1) {
        acc.x += __shfl_xor_sync(0xffffffffu, acc.x, off);
        acc.y += __shfl_xor_sync(0xffffffffu, acc.y, off);
        acc.z += __shfl_xor_sync(0xffffffffu, acc.z, off);
        acc.w += __shfl_xor_sync(0xffffffffu, acc.w, off);
    }

    // redistribute: lane L wants feature L = 4*(L>>2) + (L&3)
    int srcl = lane >> 2;                // a lane whose fl == L>>2
    float v0 = __shfl_sync(0xffffffffu, acc.x, srcl);
    float v1 = __shfl_sync(0xffffffffu, acc.y, srcl);
    float v2 = __shfl_sync(0xffffffffu, acc.z, srcl);
    float v3 = __shfl_sync(0xffffffffu, acc.w, srcl);
    int c = lane & 3;
    return (c == 0) ? v0 : (c == 1) ? v1 : (c == 2) ? v2 : v3;
}

__global__ __launch_bounds__(256) void k_pull0(const float* __restrict__ W2,
                                               const float* __restrict__ b1) {
    __shared__ float sW[F * F];
    __shared__ float sb[F];
    for (int i = threadIdx.x; i < F * F; i += blockDim.x) sW[i] = W2[i];
    if (threadIdx.x < F) sb[threadIdx.x] = b1[threadIdx.x];
    __syncthreads();

    int wid  = (blockIdx.x * blockDim.x + threadIdx.x) >> 5;
    int lane = threadIdx.x & 31;
    if (wid >= N_NODES) return;
    int v = wid;

    float di  = d_dinv[v];
    float acc = warp_gather_sum(d_g1, v, lane);
    float h   = fmaxf(di * acc + sb[lane], 0.f);

    float s = 0.f;
#pragma unroll
    for (int k = 0; k < F; k++) {
        float hk = __shfl_sync(0xffffffffu, h, k);
        s += hk * sW[k * F + lane];
    }
    d_g2[v * F + lane] = di * s;
}

__global__ __launch_bounds__(256) void k_pull1(const float* __restrict__ b2,
                                               const float* __restrict__ Wc,
                                               const float* __restrict__ bc,
                                               float* __restrict__ out) {
    __shared__ float sW[F * FOUT];
    __shared__ float sb[F];
    __shared__ float sbc[FOUT];
    for (int i = threadIdx.x; i < F * FOUT; i += blockDim.x) sW[i] = Wc[i];
    if (threadIdx.x < F)    sb[threadIdx.x]  = b2[threadIdx.x];
    if (threadIdx.x < FOUT) sbc[threadIdx.x] = bc[threadIdx.x];
    __syncthreads();

    int wid  = (blockIdx.x * blockDim.x + threadIdx.x) >> 5;
    int lane = threadIdx.x & 31;
    if (wid >= N_NODES) return;
    int v = wid;

    float di  = d_dinv[v];
    float acc = warp_gather_sum(d_g2, v, lane);
    float h   = fmaxf(di * acc + sb[lane], 0.f);

    float s = (lane < FOUT) ? sbc[lane] : 0.f;
#pragma unroll
    for (int k = 0; k < F; k++) {
        float hk = __shfl_sync(0xffffffffu, h, k);
        if (lane < FOUT) s += hk * sW[k * FOUT + lane];
    }
    if (lane < FOUT) out[v * FOUT + lane] = s;
}

// ---------------------------------------------------------------------------
extern "C" void kernel_launch(void* const* d_in, const int* in_sizes, int n_in,
                              void* d_out, int out_size) {
    const float* x  = (const float*)d_in[0];
    const int*   ei = (const int*)d_in[1];   // [2, E] row-major, int32
    const float* W1 = (const float*)d_in[3];
    const float* b1 = (const float*)d_in[4];
    const float* W2 = (const float*)d_in[5];
    const float* b2 = (const float*)d_in[6];
    const float* Wc = (const float*)d_in[7];
    const float* bc = (const float*)d_in[8];

    const int* src = ei;
    const int* dst = ei + N_EDGES;

    const int nb_node  = (N_NODES + 255) / 256;
    const int nb_edge4 = (N_EDGES / 4 + 255) / 256;
    const int nb_pull  = (N_NODES * 32 + 255) / 256;

    k_zero <<<nb_node, 256>>>();
    k_fill <<<nb_edge4, 256>>>(src, dst);
    k_node1<<<nb_node, 256>>>(x, W1);
    k_pull0<<<nb_pull, 256>>>(W2, b1);
    k_pull1<<<nb_pull, 256>>>(b2, Wc, bc, (float*)d_out);
}

// round 16
// speedup vs baseline: 1.2137x; 1.2137x over previous
#include <cuda_runtime.h>
#include <cuda_fp16.h>

#define N_NODES 100000
#define N_EDGES 6400000
#define F       32
#define FIN     10
#define FOUT    4
#define STRIDE  128   // bucket capacity; deg~Poisson(64), 8 sigma, P(ovfl)~1e-10

// Scratch (device globals; no allocation allowed)
__device__ int   d_cursor[N_NODES];
__device__ float d_dinv  [N_NODES];
__device__ uint4 d_g1    [N_NODES * 4];   // fp16 payload: 32 half = 4x uint4
__device__ uint4 d_g2    [N_NODES * 4];
__device__ int   d_csr   [N_NODES * STRIDE];

// ---------------------------------------------------------------------------
// Bucketed fill: pos = atomicAdd(cursor[dst]); csr[dst*STRIDE+pos] = src
// cursor[v] doubles as in-degree afterwards. One thread per edge: maximum
// chip-level MLP for the atomic+store round-trips.
// ---------------------------------------------------------------------------
__global__ void k_zero() {
    int v = blockIdx.x * blockDim.x + threadIdx.x;
    if (v < N_NODES) d_cursor[v] = 0;
}

__global__ __launch_bounds__(512) void k_fill(const int* __restrict__ src,
                                              const int* __restrict__ dst) {
    int e = blockIdx.x * blockDim.x + threadIdx.x;
    if (e >= N_EDGES) return;
    int s = __ldg(&src[e]);
    int d = __ldg(&dst[e]);
    d_csr[(d << 7) + atomicAdd(&d_cursor[d], 1)] = s;
}

// ---------------------------------------------------------------------------
// Layer-1 node transform: dinv = rsqrt(deg+1); g1 = fp16( dinv * (x @ W1) )
// ---------------------------------------------------------------------------
__global__ void k_node1(const float* __restrict__ x, const float* __restrict__ W1) {
    __shared__ float sW[FIN * F];
    for (int i = threadIdx.x; i < FIN * F; i += blockDim.x) sW[i] = W1[i];
    __syncthreads();

    int v = blockIdx.x * blockDim.x + threadIdx.x;
    if (v >= N_NODES) return;

    float di = rsqrtf((float)(d_cursor[v] + 1));             // +1: self loop
    d_dinv[v] = di;

    float xi[FIN];
#pragma unroll
    for (int k = 0; k < FIN; k++) xi[k] = x[v * FIN + k];

#pragma unroll
    for (int c = 0; c < 4; c++) {                            // 8 features per chunk
        float f[8];
#pragma unroll
        for (int u = 0; u < 8; u++) {
            int j = c * 8 + u;
            float s = 0.f;
#pragma unroll
            for (int k = 0; k < FIN; k++) s += xi[k] * sW[k * F + j];
            f[u] = s * di;
        }
        uint4 p;
        ((__half2*)&p)[0] = __floats2half2_rn(f[0], f[1]);
        ((__half2*)&p)[1] = __floats2half2_rn(f[2], f[3]);
        ((__half2*)&p)[2] = __floats2half2_rn(f[4], f[5]);
        ((__half2*)&p)[3] = __floats2half2_rn(f[6], f[7]);
        d_g1[v * 4 + c] = p;
    }
}

// ---------------------------------------------------------------------------
// Pull-gather: warp per node; 4 lanes per edge (16B fp16 chunk each).
// One warp LDG.128 covers 8 edges. Explicit 4-deep load pipeline (MLP=4).
// fp32 accumulate. Returns: lane L holds accumulated feature L.
// ---------------------------------------------------------------------------
__device__ __forceinline__ void acc_chunk(float* a, uint4 p) {
    const __half2* ph = (const __half2*)&p;
    float2 f0 = __half22float2(ph[0]);
    float2 f1 = __half22float2(ph[1]);
    float2 f2 = __half22float2(ph[2]);
    float2 f3 = __half22float2(ph[3]);
    a[0] += f0.x; a[1] += f0.y; a[2] += f1.x; a[3] += f1.y;
    a[4] += f2.x; a[5] += f2.y; a[6] += f3.x; a[7] += f3.y;
}

__device__ __forceinline__ float warp_gather_sum(const uint4* __restrict__ gv,
                                                 int v, int lane) {
    const int beg = v << 7;             // v * STRIDE
    const int cnt = d_cursor[v];
    const int end = beg + cnt;
    const int q   = lane >> 2;          // edge slot 0..7
    const int fl  = lane & 3;           // 16B feature chunk 0..3

    float a[8] = {0.f, 0.f, 0.f, 0.f, 0.f, 0.f, 0.f, 0.f};

    int e = beg;
    for (; e + 32 <= end; e += 32) {
        int my_s = __ldg(&d_csr[e + lane]);
        // issue all shuffles, then all loads: 4 LDG.128 in flight per warp
        int s0 = __shfl_sync(0xffffffffu, my_s,  0 + q);
        int s1 = __shfl_sync(0xffffffffu, my_s,  8 + q);
        int s2 = __shfl_sync(0xffffffffu, my_s, 16 + q);
        int s3 = __shfl_sync(0xffffffffu, my_s, 24 + q);
        uint4 p0 = __ldg(&gv[s0 * 4 + fl]);
        uint4 p1 = __ldg(&gv[s1 * 4 + fl]);
        uint4 p2 = __ldg(&gv[s2 * 4 + fl]);
        uint4 p3 = __ldg(&gv[s3 * 4 + fl]);
        acc_chunk(a, p0);
        acc_chunk(a, p1);
        acc_chunk(a, p2);
        acc_chunk(a, p3);
    }
    int rem = end - e;
    if (rem > 0) {
        int my_s = (lane < rem) ? __ldg(&d_csr[e + lane]) : 0;
        int nj = (rem + 7) >> 3;
        for (int j = 0; j < nj; j++) {
            int idx = j * 8 + q;
            int s = __shfl_sync(0xffffffffu, my_s, idx < rem ? idx : 0);
            if (idx < rem) acc_chunk(a, __ldg(&gv[s * 4 + fl]));
        }
    }
    if (q == 0) acc_chunk(a, __ldg(&gv[v * 4 + fl]));   // self loop

    // fold the 8 edge slots (lane bits 2,3,4)
#pragma unroll
    for (int off = 4; off < 32; off <<= 1) {
#pragma unroll
        for (int r = 0; r < 8; r++)
            a[r] += __shfl_xor_sync(0xffffffffu, a[r], off);
    }

    // redistribute: lane L wants feature L = (L>>3)*8 + (L&7); chunk holder = lane L>>3
    int srcl = lane >> 3;
    float w[8];
#pragma unroll
    for (int r = 0; r < 8; r++)
        w[r] = __shfl_sync(0xffffffffu, a[r], srcl);
    int k = lane & 7;
    float lo = (k & 2) ? ((k & 1) ? w[3] : w[2]) : ((k & 1) ? w[1] : w[0]);
    float hi = (k & 2) ? ((k & 1) ? w[7] : w[6]) : ((k & 1) ? w[5] : w[4]);
    return (k & 4) ? hi : lo;
}

__global__ __launch_bounds__(256) void k_pull0(const float* __restrict__ W2,
                                               const float* __restrict__ b1) {
    __shared__ float sW[F * F];
    __shared__ float sb[F];
    for (int i = threadIdx.x; i < F * F; i += blockDim.x) sW[i] = W2[i];
    if (threadIdx.x < F) sb[threadIdx.x] = b1[threadIdx.x];
    __syncthreads();

    int wid  = (blockIdx.x * blockDim.x + threadIdx.x) >> 5;
    int lane = threadIdx.x & 31;
    if (wid >= N_NODES) return;
    int v = wid;

    float di  = d_dinv[v];
    float acc = warp_gather_sum(d_g1, v, lane);
    float h   = fmaxf(di * acc + sb[lane], 0.f);

    float s = 0.f;
#pragma unroll
    for (int k = 0; k < F; k++) {
        float hk = __shfl_sync(0xffffffffu, h, k);
        s += hk * sW[k * F + lane];
    }
    ((__half*)d_g2)[v * F + lane] = __float2half_rn(di * s);
}

__global__ __launch_bounds__(256) void k_pull1(const float* __restrict__ b2,
                                               const float* __restrict__ Wc,
                                               const float* __restrict__ bc,
                                               float* __restrict__ out) {
    __shared__ float sW[F * FOUT];
    __shared__ float sb[F];
    __shared__ float sbc[FOUT];
    for (int i = threadIdx.x; i < F * FOUT; i += blockDim.x) sW[i] = Wc[i];
    if (threadIdx.x < F)    sb[threadIdx.x]  = b2[threadIdx.x];
    if (threadIdx.x < FOUT) sbc[threadIdx.x] = bc[threadIdx.x];
    __syncthreads();

    int wid  = (blockIdx.x * blockDim.x + threadIdx.x) >> 5;
    int lane = threadIdx.x & 31;
    if (wid >= N_NODES) return;
    int v = wid;

    float di  = d_dinv[v];
    float acc = warp_gather_sum(d_g2, v, lane);
    float h   = fmaxf(di * acc + sb[lane], 0.f);

    float s = (lane < FOUT) ? sbc[lane] : 0.f;
#pragma unroll
    for (int k = 0; k < F; k++) {
        float hk = __shfl_sync(0xffffffffu, h, k);
        if (lane < FOUT) s += hk * sW[k * FOUT + lane];
    }
    if (lane < FOUT) out[v * FOUT + lane] = s;
}

// ---------------------------------------------------------------------------
extern "C" void kernel_launch(void* const* d_in, const int* in_sizes, int n_in,
                              void* d_out, int out_size) {
    const float* x  = (const float*)d_in[0];
    const int*   ei = (const int*)d_in[1];   // [2, E] row-major, int32
    const float* W1 = (const float*)d_in[3];
    const float* b1 = (const float*)d_in[4];
    const float* W2 = (const float*)d_in[5];
    const float* b2 = (const float*)d_in[6];
    const float* Wc = (const float*)d_in[7];
    const float* bc = (const float*)d_in[8];

    const int* src = ei;
    const int* dst = ei + N_EDGES;

    const int nb_node = (N_NODES + 255) / 256;
    const int nb_edge = (N_EDGES + 511) / 512;
    const int nb_pull = (N_NODES * 32 + 255) / 256;

    k_zero <<<nb_node, 256>>>();
    k_fill <<<nb_edge, 512>>>(src, dst);
    k_node1<<<nb_node, 256>>>(x, W1);
    k_pull0<<<nb_pull, 256>>>(W2, b1);
    k_pull1<<<nb_pull, 256>>>(b2, Wc, bc, (float*)d_out);
}